// round 6
// baseline (speedup 1.0000x reference)
#include <cuda_runtime.h>
#include <cuda_fp16.h>
#include <math.h>
#include <stdint.h>

#define NB      4
#define TSEQ    2048
#define NHEAD   16
#define HD      64
#define DMODEL  1024
#define ROWS    (NB * TSEQ)          // 8192
#define QKVCOLS (3 * DMODEL)         // 3072
#define WIN     128

// ---------------- scratch (allocation-free rule: device globals) ----------
__device__ __align__(16) __half g_qkvh[ROWS * QKVCOLS];  // [b,t, 3,h,d] fp16 (un-roped)
__device__ __align__(16) __half g_Ah[ROWS   * DMODEL];
__device__ __align__(16) __half g_Al[ROWS   * DMODEL];
__device__ __align__(16) __half g_Bh[QKVCOLS * DMODEL];  // [N][K] transposed fp16
__device__ float4 g_rope[TSEQ * 16];  // (t, pg): cos/sin for freqs 2pg, 2pg+1

// ---------------- PTX helpers ---------------------------------------------
__device__ __forceinline__ uint32_t smem_u32(const void* p) {
    uint32_t a;
    asm("{ .reg .u64 t; cvta.to.shared.u64 t, %1; cvt.u32.u64 %0, t; }" : "=r"(a) : "l"(p));
    return a;
}
__device__ __forceinline__ void cp16(uint32_t dst, const void* src) {
    asm volatile("cp.async.cg.shared.global [%0], [%1], 16;" :: "r"(dst), "l"(src));
}
#define CP_COMMIT() asm volatile("cp.async.commit_group;" ::: "memory")
#define CP_WAIT(n)  asm volatile("cp.async.wait_group %0;" :: "n"(n) : "memory")

#define LDSM_X4(r, addr) \
    asm volatile("ldmatrix.sync.aligned.m8n8.x4.shared.b16 {%0,%1,%2,%3}, [%4];" \
        : "=r"((r)[0]), "=r"((r)[1]), "=r"((r)[2]), "=r"((r)[3]) : "r"(addr))
#define LDSM_X4_T(r, addr) \
    asm volatile("ldmatrix.sync.aligned.m8n8.x4.trans.shared.b16 {%0,%1,%2,%3}, [%4];" \
        : "=r"((r)[0]), "=r"((r)[1]), "=r"((r)[2]), "=r"((r)[3]) : "r"(addr))

#define MMA_F16(c, a, b0, b1) \
    asm volatile("mma.sync.aligned.m16n8k16.row.col.f32.f16.f16.f32 " \
        "{%0,%1,%2,%3}, {%4,%5,%6,%7}, {%8,%9}, {%0,%1,%2,%3};" \
        : "+f"((c)[0]), "+f"((c)[1]), "+f"((c)[2]), "+f"((c)[3]) \
        : "r"((a)[0]), "r"((a)[1]), "r"((a)[2]), "r"((a)[3]), "r"(b0), "r"(b1))

__device__ __forceinline__ uint32_t packh2(float a, float b) {
    __half2 h = __floats2half2_rn(a, b);
    return *reinterpret_cast<uint32_t*>(&h);
}

// ---------------- mma.sync GEMM: C = A[M,K]*Bt[N,K]^T, fp16 2-term A -------
// CTA tile 128x256, 8 warps (2m x 4n), warp tile 64x64. 3-stage cp.async.
#define BM 128
#define BN 256
#define BK 32
#define PADK 40
#define A_BYTES (128 * PADK * 2)      // 10240
#define B_BYTES (256 * PADK * 2)      // 20480
#define SM_AH 0
#define SM_AL A_BYTES
#define SM_BH (2 * A_BYTES)
#define STAGE_BYTES (2 * A_BYTES + B_BYTES)   // 40960
#define GEMM_SMEM (3 * STAGE_BYTES)           // 122880

__device__ __forceinline__ void load_chunk(
    uint32_t sb, const __half* __restrict__ Ah, const __half* __restrict__ Al,
    const __half* __restrict__ Bh,
    int brow, int bcol, int K, int kc, int stage, int tid)
{
    uint32_t base = sb + stage * STAGE_BYTES;
    // A: 128 rows x 32k (64B = 4 chunks/row) -> 512 cp16 per matrix
#pragma unroll
    for (int t = 0; t < 2; t++) {
        int idx = tid + t * 256;
        int row = idx >> 2;
        int c16 = idx & 3;
        uint32_t so = (uint32_t)(row * (PADK * 2) + c16 * 16);
        size_t ga = (size_t)(brow + row) * K + kc + c16 * 8;
        cp16(base + SM_AH + so, Ah + ga);
        cp16(base + SM_AL + so, Al + ga);
    }
    // B: 256 rows x 32k -> 1024 cp16
#pragma unroll
    for (int t = 0; t < 4; t++) {
        int idx = tid + t * 256;
        int row = idx >> 2;
        int c16 = idx & 3;
        uint32_t so = (uint32_t)(row * (PADK * 2) + c16 * 16);
        size_t gb = (size_t)(bcol + row) * K + kc + c16 * 8;
        cp16(base + SM_BH + so, Bh + gb);
    }
}

__global__ __launch_bounds__(256, 1)
void gemm_mma(const __half* __restrict__ Ah, const __half* __restrict__ Al,
              const __half* __restrict__ Bh,
              float* __restrict__ C, __half* __restrict__ Chalf,
              int M, int N, int K, const float* __restrict__ bias)
{
    extern __shared__ __align__(128) char smem[];
    uint32_t sb = smem_u32(smem);
    const int tid  = threadIdx.x;
    const int wid  = tid >> 5;
    const int lane = tid & 31;
    const int wm = (wid >> 2) * 64;     // 2 warp-rows
    const int wn = (wid & 3) * 64;      // 4 warp-cols
    const int brow = blockIdx.y * BM, bcol = blockIdx.x * BN;

    float c[4][8][4];
#pragma unroll
    for (int i = 0; i < 4; i++)
#pragma unroll
        for (int j = 0; j < 8; j++)
#pragma unroll
            for (int r = 0; r < 4; r++) c[i][j][r] = 0.0f;

    const int nchunks = K / BK;
    load_chunk(sb, Ah, Al, Bh, brow, bcol, K, 0, 0, tid);
    CP_COMMIT();
    load_chunk(sb, Ah, Al, Bh, brow, bcol, K, BK, 1, tid);
    CP_COMMIT();

    const int a_r = lane & 15;
    const int a_c = (lane >> 4) << 3;
    const int b_r = ((lane < 16) ? (lane & 7) : (8 + (lane & 7)));
    const int b_c = ((lane >> 3) & 1) << 3;

    for (int ch = 0; ch < nchunks; ch++) {
        if (ch + 1 < nchunks) { CP_WAIT(1); } else { CP_WAIT(0); }
        __syncthreads();
        if (ch + 2 < nchunks) {
            load_chunk(sb, Ah, Al, Bh, brow, bcol, K, (ch + 2) * BK, (ch + 2) % 3, tid);
            CP_COMMIT();
        }
        uint32_t stb = sb + (ch % 3) * STAGE_BYTES;
#pragma unroll
        for (int ks = 0; ks < 2; ks++) {
            const int kb = ks * 16;
            uint32_t ah[4][4], al[4][4], bh[4][4];
#pragma unroll
            for (int mt = 0; mt < 4; mt++) {
                uint32_t ad = stb + SM_AH +
                    (uint32_t)((wm + mt * 16 + a_r) * (PADK * 2) + (kb + a_c) * 2);
                LDSM_X4(ah[mt], ad);
                LDSM_X4(al[mt], ad + (SM_AL - SM_AH));
            }
#pragma unroll
            for (int nt = 0; nt < 4; nt++) {
                uint32_t bd = stb + SM_BH +
                    (uint32_t)((wn + nt * 16 + b_r) * (PADK * 2) + (kb + b_c) * 2);
                LDSM_X4(bh[nt], bd);
            }
            // term h for all tiles, then term l: no back-to-back same-acc MMAs
#pragma unroll
            for (int mt = 0; mt < 4; mt++)
#pragma unroll
                for (int n8 = 0; n8 < 8; n8++)
                    MMA_F16(c[mt][n8], ah[mt],
                            bh[n8 >> 1][(n8 & 1) * 2], bh[n8 >> 1][(n8 & 1) * 2 + 1]);
#pragma unroll
            for (int mt = 0; mt < 4; mt++)
#pragma unroll
                for (int n8 = 0; n8 < 8; n8++)
                    MMA_F16(c[mt][n8], al[mt],
                            bh[n8 >> 1][(n8 & 1) * 2], bh[n8 >> 1][(n8 & 1) * 2 + 1]);
        }
    }

#pragma unroll
    for (int mt = 0; mt < 4; mt++) {
        int row0 = brow + wm + mt * 16 + (lane >> 2);
#pragma unroll
        for (int n8 = 0; n8 < 8; n8++) {
            int col = bcol + wn + n8 * 8 + (lane & 3) * 2;
            if (Chalf) {
                *(__half2*)(Chalf + (size_t)row0 * N + col) =
                    __floats2half2_rn(c[mt][n8][0], c[mt][n8][1]);
                *(__half2*)(Chalf + (size_t)(row0 + 8) * N + col) =
                    __floats2half2_rn(c[mt][n8][2], c[mt][n8][3]);
            } else {
                float bx = 0.f, by = 0.f;
                if (bias) { bx = bias[col]; by = bias[col + 1]; }
                *(float2*)(C + (size_t)row0 * N + col) =
                    make_float2(c[mt][n8][0] + bx, c[mt][n8][1] + by);
                *(float2*)(C + (size_t)(row0 + 8) * N + col) =
                    make_float2(c[mt][n8][2] + bx, c[mt][n8][3] + by);
            }
        }
    }
}

// ---------------- fp32 -> fp16 hi/lo split (x input only) -------------------
__global__ void split_a(const float* __restrict__ src,
                        __half* __restrict__ h, __half* __restrict__ l, int n)
{
    int i = blockIdx.x * blockDim.x + threadIdx.x;
    if (i >= n) return;
    float v = src[i];
    __half hb = __float2half(v);
    h[i] = hb;
    l[i] = __float2half(v - __half2float(hb));
}

// W[K][N] -> Bt[N][K] fp16, smem-tiled transpose
__global__ void wconv(const float* __restrict__ W, __half* __restrict__ Bt, int K, int N)
{
    __shared__ float tile[32][33];
    int n0 = blockIdx.x * 32, k0 = blockIdx.y * 32;
    int tx = threadIdx.x & 31, ty = threadIdx.x >> 5;
#pragma unroll
    for (int r = 0; r < 4; r++)
        tile[ty + 8 * r][tx] = W[(size_t)(k0 + ty + 8 * r) * N + n0 + tx];
    __syncthreads();
#pragma unroll
    for (int r = 0; r < 4; r++)
        Bt[(size_t)(n0 + ty + 8 * r) * K + k0 + tx] = __float2half(tile[tx][ty + 8 * r]);
}

// ---------------- RoPE cos/sin table ----------------------------------------
__global__ void rope_table()
{
    int idx = blockIdx.x * blockDim.x + threadIdx.x;
    if (idx >= TSEQ * 16) return;
    int t = idx >> 4, pg = idx & 15;
    float c0, s0, c1, s1;
    {
        float e = (float)(2 * (2 * pg)) * (1.0f / 64.0f);
        float ang = (float)t * exp2f(-e * 13.2877123795494493f);
        sincosf(ang, &s0, &c0);
    }
    {
        float e = (float)(2 * (2 * pg + 1)) * (1.0f / 64.0f);
        float ang = (float)t * exp2f(-e * 13.2877123795494493f);
        sincosf(ang, &s1, &c1);
    }
    g_rope[idx] = make_float4(c0, s0, c1, s1);
}

// ---------------- flash attention via mma.sync -------------------------------
#define PADH 72
#define QS_BYTES (64 * PADH * 2)        // 9216
#define KS_OFF   QS_BYTES
#define KS_BYTES (320 * PADH * 2)       // 46080
#define VS_OFF   (KS_OFF + KS_BYTES)
#define ATTN_SMEM (VS_OFF + KS_BYTES)   // 101376

__global__ __launch_bounds__(256, 2)
void attn_kernel()
{
    extern __shared__ __align__(128) char asmem[];
    uint32_t sb = smem_u32(asmem);
    __half* Qs  = (__half*)asmem;
    __half* Ksm = (__half*)(asmem + KS_OFF);
    __half* Vsm = (__half*)(asmem + VS_OFF);
    float*  mgb = (float*)(asmem + KS_OFF);   // merge buffer aliases Ks

    const int tid = threadIdx.x, wid = tid >> 5, lane = tid & 31;
    const int b = blockIdx.z, h = blockIdx.y;
    const int t0 = blockIdx.x * 64;
    const int warp_m = wid & 3, warp_n = wid >> 2;

    const __half* qkbase = g_qkvh + (size_t)b * TSEQ * QKVCOLS + h * HD;

    for (int idx = tid; idx < 64 * 16; idx += 256) {
        int qr = idx >> 4, pg = idx & 15;
        int t = t0 + qr;
        const __half* src = qkbase + (size_t)t * QKVCOLS;
        float2 u = __half22float2(*(const __half2*)(src + 2 * pg));
        float2 w = __half22float2(*(const __half2*)(src + 2 * pg + 32));
        float4 cs = g_rope[t * 16 + pg];
        *(__half2*)(Qs + qr * PADH + 2 * pg) = __floats2half2_rn(
            0.125f * (u.x * cs.x - w.x * cs.y), 0.125f * (u.y * cs.z - w.y * cs.w));
        *(__half2*)(Qs + qr * PADH + 2 * pg + 32) = __floats2half2_rn(
            0.125f * (u.x * cs.y + w.x * cs.x), 0.125f * (u.y * cs.w + w.y * cs.z));
    }
    for (int idx = tid; idx < 320 * 16; idx += 256) {
        int kk = idx >> 4, pg = idx & 15;
        int kg = t0 - 128 + kk;
        kg = kg < 0 ? 0 : (kg > TSEQ - 1 ? TSEQ - 1 : kg);
        const __half* src = qkbase + (size_t)kg * QKVCOLS + DMODEL;
        float2 u = __half22float2(*(const __half2*)(src + 2 * pg));
        float2 w = __half22float2(*(const __half2*)(src + 2 * pg + 32));
        float4 cs = g_rope[kg * 16 + pg];
        *(__half2*)(Ksm + kk * PADH + 2 * pg) = __floats2half2_rn(
            u.x * cs.x - w.x * cs.y, u.y * cs.z - w.y * cs.w);
        *(__half2*)(Ksm + kk * PADH + 2 * pg + 32) = __floats2half2_rn(
            u.x * cs.y + w.x * cs.x, u.y * cs.w + w.y * cs.z);
    }
    for (int idx = tid; idx < 320 * 8; idx += 256) {
        int kk = idx >> 3, grp = idx & 7;
        int kg = t0 - 128 + kk;
        kg = kg < 0 ? 0 : (kg > TSEQ - 1 ? TSEQ - 1 : kg);
        const __half* src = qkbase + (size_t)kg * QKVCOLS + 2 * DMODEL + 8 * grp;
        *(int4*)(Vsm + kk * PADH + 8 * grp) = *(const int4*)src;
    }
    __syncthreads();

    const int a_r = lane & 15;
    const int a_c = (lane >> 4) << 3;
    const int b_r = ((lane < 16) ? (lane & 7) : (8 + (lane & 7)));
    const int b_c = ((lane >> 3) & 1) << 3;
    const int qlo = t0 + warp_m * 16;
    const int qi0 = qlo + (lane >> 2);

    float m0 = -1e30f, m1 = -1e30f, l0 = 0.f, l1 = 0.f;
    float o[8][4];
#pragma unroll
    for (int t = 0; t < 8; t++)
#pragma unroll
        for (int j = 0; j < 4; j++) o[t][j] = 0.f;

    for (int c = 0; c < 5; c++) {
        int kk0 = 64 * c + 32 * warp_n;
        int kgb = t0 - 128 + kk0;
        if (kgb + 31 < qlo - WIN || kgb > qlo + 15 + WIN) continue;

        float cS[4][4];
#pragma unroll
        for (int i = 0; i < 4; i++)
#pragma unroll
            for (int j = 0; j < 4; j++) cS[i][j] = 0.f;
#pragma unroll
        for (int ks = 0; ks < 4; ks++) {
            uint32_t aq[4], bk0[4], bk1[4];
            LDSM_X4(aq, sb + (uint32_t)((warp_m * 16 + a_r) * PADH + ks * 16 + a_c) * 2);
            LDSM_X4(bk0, sb + KS_OFF + (uint32_t)((kk0 + b_r) * PADH + ks * 16 + b_c) * 2);
            LDSM_X4(bk1, sb + KS_OFF + (uint32_t)((kk0 + 16 + b_r) * PADH + ks * 16 + b_c) * 2);
            MMA_F16(cS[0], aq, bk0[0], bk0[1]);
            MMA_F16(cS[1], aq, bk0[2], bk0[3]);
            MMA_F16(cS[2], aq, bk1[0], bk1[1]);
            MMA_F16(cS[3], aq, bk1[2], bk1[3]);
        }

        float rmax0 = -1e30f, rmax1 = -1e30f;
#pragma unroll
        for (int n8 = 0; n8 < 4; n8++) {
            int jb = kgb + 8 * n8 + 2 * (lane & 3);
#pragma unroll
            for (int e = 0; e < 2; e++) {
                int j = jb + e;
                bool okj = (j >= 0) && (j < TSEQ);
                if (!(okj && j >= qi0 - WIN && j <= qi0 + WIN))         cS[n8][e]     = -1e30f;
                if (!(okj && j >= qi0 + 8 - WIN && j <= qi0 + 8 + WIN)) cS[n8][e + 2] = -1e30f;
            }
            rmax0 = fmaxf(rmax0, fmaxf(cS[n8][0], cS[n8][1]));
            rmax1 = fmaxf(rmax1, fmaxf(cS[n8][2], cS[n8][3]));
        }
        rmax0 = fmaxf(rmax0, __shfl_xor_sync(0xffffffffu, rmax0, 1));
        rmax0 = fmaxf(rmax0, __shfl_xor_sync(0xffffffffu, rmax0, 2));
        rmax1 = fmaxf(rmax1, __shfl_xor_sync(0xffffffffu, rmax1, 1));
        rmax1 = fmaxf(rmax1, __shfl_xor_sync(0xffffffffu, rmax1, 2));

        float mn0 = fmaxf(m0, rmax0), mn1 = fmaxf(m1, rmax1);
        float sc0 = __expf(m0 - mn0), sc1 = __expf(m1 - mn1);
        m0 = mn0; m1 = mn1;

        float ps0 = 0.f, ps1 = 0.f;
        uint32_t pa[4][2];
#pragma unroll
        for (int n8 = 0; n8 < 4; n8++) {
            float p0 = (cS[n8][0] < -1e29f) ? 0.f : __expf(cS[n8][0] - mn0);
            float p1 = (cS[n8][1] < -1e29f) ? 0.f : __expf(cS[n8][1] - mn0);
            float p2 = (cS[n8][2] < -1e29f) ? 0.f : __expf(cS[n8][2] - mn1);
            float p3 = (cS[n8][3] < -1e29f) ? 0.f : __expf(cS[n8][3] - mn1);
            ps0 += p0 + p1; ps1 += p2 + p3;
            pa[n8][0] = packh2(p0, p1);
            pa[n8][1] = packh2(p2, p3);
        }
        ps0 += __shfl_xor_sync(0xffffffffu, ps0, 1);
        ps0 += __shfl_xor_sync(0xffffffffu, ps0, 2);
        ps1 += __shfl_xor_sync(0xffffffffu, ps1, 1);
        ps1 += __shfl_xor_sync(0xffffffffu, ps1, 2);
        l0 = l0 * sc0 + ps0;
        l1 = l1 * sc1 + ps1;
#pragma unroll
        for (int t = 0; t < 8; t++) {
            o[t][0] *= sc0; o[t][1] *= sc0; o[t][2] *= sc1; o[t][3] *= sc1;
        }

#pragma unroll
        for (int kp = 0; kp < 2; kp++) {
            uint32_t a[4] = { pa[2 * kp][0], pa[2 * kp][1], pa[2 * kp + 1][0], pa[2 * kp + 1][1] };
#pragma unroll
            for (int np = 0; np < 4; np++) {
                uint32_t bv[4];
                LDSM_X4_T(bv, sb + VS_OFF +
                    (uint32_t)((kk0 + kp * 16 + a_r) * PADH + np * 16 + a_c) * 2);
                MMA_F16(o[2 * np],     a, bv[0], bv[1]);
                MMA_F16(o[2 * np + 1], a, bv[2], bv[3]);
            }
        }
    }

    __syncthreads();
    float* ob = mgb + (warp_m * 32 + lane) * 33;
    float2* mlb = (float2*)(mgb + 4 * 32 * 33);
    if (warp_n == 1) {
#pragma unroll
        for (int t = 0; t < 8; t++)
#pragma unroll
            for (int j = 0; j < 4; j++) ob[4 * t + j] = o[t][j];
        if ((lane & 3) == 0) {
            mlb[warp_m * 16 + (lane >> 2)]     = make_float2(m0, l0);
            mlb[warp_m * 16 + 8 + (lane >> 2)] = make_float2(m1, l1);
        }
    }
    __syncthreads();
    if (warp_n == 0) {
        float2 M0 = mlb[warp_m * 16 + (lane >> 2)];
        float2 M1 = mlb[warp_m * 16 + 8 + (lane >> 2)];
        float mm0 = fmaxf(m0, M0.x), mm1 = fmaxf(m1, M1.x);
        float w00 = __expf(m0 - mm0), w01 = __expf(M0.x - mm0);
        float w10 = __expf(m1 - mm1), w11 = __expf(M1.x - mm1);
        float inv0 = 1.0f / (l0 * w00 + M0.y * w01);
        float inv1 = 1.0f / (l1 * w10 + M1.y * w11);
        size_t r0 = (size_t)(b * TSEQ + qlo + (lane >> 2)) * DMODEL;
        size_t r1 = r0 + 8 * DMODEL;
#pragma unroll
        for (int t = 0; t < 8; t++) {
            int col = h * HD + t * 8 + 2 * (lane & 3);
            float v0 = (o[t][0] * w00 + ob[4 * t + 0] * w01) * inv0;
            float v1 = (o[t][1] * w00 + ob[4 * t + 1] * w01) * inv0;
            float v2 = (o[t][2] * w10 + ob[4 * t + 2] * w11) * inv1;
            float v3 = (o[t][3] * w10 + ob[4 * t + 3] * w11) * inv1;
            __half h0 = __float2half(v0), h1 = __float2half(v1);
            __half h2 = __float2half(v2), h3 = __float2half(v3);
            *(__half2*)(g_Ah + r0 + col) = __halves2half2(h0, h1);
            *(__half2*)(g_Ah + r1 + col) = __halves2half2(h2, h3);
            *(__half2*)(g_Al + r0 + col) = __halves2half2(
                __float2half(v0 - __half2float(h0)), __float2half(v1 - __half2float(h1)));
            *(__half2*)(g_Al + r1 + col) = __halves2half2(
                __float2half(v2 - __half2float(h2)), __float2half(v3 - __half2float(h3)));
        }
    }
}

// ---------------------------------------------------------------------------
extern "C" void kernel_launch(void* const* d_in, const int* in_sizes, int n_in,
                              void* d_out, int out_size)
{
    const float* x    = (const float*)d_in[0];
    const float* Wqkv = (const float*)d_in[1];
    const float* Wout = (const float*)d_in[2];
    const float* bout = (const float*)d_in[3];
    float* out = (float*)d_out;

    __half *qkvh, *Ah, *Al, *Bh;
    cudaGetSymbolAddress((void**)&qkvh, g_qkvh);
    cudaGetSymbolAddress((void**)&Ah, g_Ah);
    cudaGetSymbolAddress((void**)&Al, g_Al);
    cudaGetSymbolAddress((void**)&Bh, g_Bh);

    cudaFuncSetAttribute(gemm_mma, cudaFuncAttributeMaxDynamicSharedMemorySize, GEMM_SMEM);
    cudaFuncSetAttribute(attn_kernel, cudaFuncAttributeMaxDynamicSharedMemorySize, ATTN_SMEM);

    rope_table<<<(TSEQ * 16 + 255) / 256, 256>>>();

    split_a<<<(ROWS * DMODEL + 511) / 512, 512>>>(x, Ah, Al, ROWS * DMODEL);
    wconv<<<dim3(QKVCOLS / 32, DMODEL / 32), 256>>>(Wqkv, Bh, DMODEL, QKVCOLS);
    gemm_mma<<<dim3(QKVCOLS / BN, ROWS / BM), 256, GEMM_SMEM>>>(
        Ah, Al, Bh, nullptr, qkvh, ROWS, QKVCOLS, DMODEL, nullptr);

    attn_kernel<<<dim3(TSEQ / 64, NHEAD, NB), 256, ATTN_SMEM>>>();

    wconv<<<dim3(DMODEL / 32, DMODEL / 32), 256>>>(Wout, Bh, DMODEL, DMODEL);
    gemm_mma<<<dim3(DMODEL / BN, ROWS / BM), 256, GEMM_SMEM>>>(
        Ah, Al, Bh, out, nullptr, ROWS, DMODEL, DMODEL, bout);
}

// round 7
// speedup vs baseline: 1.1833x; 1.1833x over previous
#include <cuda_runtime.h>
#include <cuda_fp16.h>
#include <math.h>
#include <stdint.h>

#define NB      4
#define TSEQ    2048
#define NHEAD   16
#define HD      64
#define DMODEL  1024
#define ROWS    (NB * TSEQ)          // 8192
#define QKVCOLS (3 * DMODEL)         // 3072
#define WIN     128

// ---------------- scratch (allocation-free rule: device globals) ----------
__device__ __align__(16) __half g_qkvh[ROWS * QKVCOLS];  // [b,t, 3,h,d] fp16 (un-roped)
__device__ __align__(16) __half g_Ah[ROWS   * DMODEL];
__device__ __align__(16) __half g_Al[ROWS   * DMODEL];
__device__ __align__(16) __half g_Bh[QKVCOLS * DMODEL];  // [N][K] transposed fp16
__device__ __align__(16) __half g_qr[ROWS * DMODEL];     // [b,h][t][d] roped+scaled Q
__device__ __align__(16) __half g_kr[ROWS * DMODEL];     // [b,h][t][d] roped K
__device__ __align__(16) __half g_vp[ROWS * DMODEL];     // [b,h][t][d] packed V
__device__ float4 g_rope[TSEQ * 16];  // (t, pg): cos/sin for freqs 2pg, 2pg+1

// ---------------- PTX helpers ---------------------------------------------
__device__ __forceinline__ uint32_t smem_u32(const void* p) {
    uint32_t a;
    asm("{ .reg .u64 t; cvta.to.shared.u64 t, %1; cvt.u32.u64 %0, t; }" : "=r"(a) : "l"(p));
    return a;
}
__device__ __forceinline__ void cp16(uint32_t dst, const void* src) {
    asm volatile("cp.async.cg.shared.global [%0], [%1], 16;" :: "r"(dst), "l"(src));
}
#define CP_COMMIT() asm volatile("cp.async.commit_group;" ::: "memory")
#define CP_WAIT(n)  asm volatile("cp.async.wait_group %0;" :: "n"(n) : "memory")

#define LDSM_X4(r, addr) \
    asm volatile("ldmatrix.sync.aligned.m8n8.x4.shared.b16 {%0,%1,%2,%3}, [%4];" \
        : "=r"((r)[0]), "=r"((r)[1]), "=r"((r)[2]), "=r"((r)[3]) : "r"(addr))
#define LDSM_X4_T(r, addr) \
    asm volatile("ldmatrix.sync.aligned.m8n8.x4.trans.shared.b16 {%0,%1,%2,%3}, [%4];" \
        : "=r"((r)[0]), "=r"((r)[1]), "=r"((r)[2]), "=r"((r)[3]) : "r"(addr))

#define MMA_F16(c, a, b0, b1) \
    asm volatile("mma.sync.aligned.m16n8k16.row.col.f32.f16.f16.f32 " \
        "{%0,%1,%2,%3}, {%4,%5,%6,%7}, {%8,%9}, {%0,%1,%2,%3};" \
        : "+f"((c)[0]), "+f"((c)[1]), "+f"((c)[2]), "+f"((c)[3]) \
        : "r"((a)[0]), "r"((a)[1]), "r"((a)[2]), "r"((a)[3]), "r"(b0), "r"(b1))

__device__ __forceinline__ uint32_t packh2(float a, float b) {
    __half2 h = __floats2half2_rn(a, b);
    return *reinterpret_cast<uint32_t*>(&h);
}

// ---------------- mma.sync GEMM: C = A[M,K]*Bt[N,K]^T, fp16 2-term A -------
// CTA 128x128, 8 warps (4m x 2n), warp tile 32x64, 3-stage cp.async, <=128 regs.
#define BM 128
#define BN 128
#define BK 32
#define PADK 40
#define MAT_BYTES (128 * PADK * 2)    // 10240
#define SM_AH 0
#define SM_AL (1 * MAT_BYTES)
#define SM_BH (2 * MAT_BYTES)
#define STAGE_BYTES (3 * MAT_BYTES)   // 30720
#define GEMM_SMEM (3 * STAGE_BYTES)   // 92160

__device__ __forceinline__ void load_chunk(
    uint32_t sb, const __half* __restrict__ Ah, const __half* __restrict__ Al,
    const __half* __restrict__ Bh,
    int brow, int bcol, int K, int kc, int stage, int tid)
{
    uint32_t base = sb + stage * STAGE_BYTES;
#pragma unroll
    for (int t = 0; t < 2; t++) {
        int idx = tid + t * 256;
        int row = idx >> 2;
        int c16 = idx & 3;
        uint32_t so = (uint32_t)(row * (PADK * 2) + c16 * 16);
        size_t ga = (size_t)(brow + row) * K + kc + c16 * 8;
        size_t gb = (size_t)(bcol + row) * K + kc + c16 * 8;
        cp16(base + SM_AH + so, Ah + ga);
        cp16(base + SM_AL + so, Al + ga);
        cp16(base + SM_BH + so, Bh + gb);
    }
}

__global__ __launch_bounds__(256, 2)
void gemm_mma(const __half* __restrict__ Ah, const __half* __restrict__ Al,
              const __half* __restrict__ Bh,
              float* __restrict__ C, __half* __restrict__ Chalf,
              int M, int N, int K, const float* __restrict__ bias)
{
    extern __shared__ __align__(128) char smem[];
    uint32_t sb = smem_u32(smem);
    const int tid  = threadIdx.x;
    const int wid  = tid >> 5;
    const int lane = tid & 31;
    const int wm = (wid & 3) * 32;      // 4 warp-rows
    const int wn = (wid >> 2) * 64;     // 2 warp-cols
    const int brow = blockIdx.y * BM, bcol = blockIdx.x * BN;

    float c[2][8][4];
#pragma unroll
    for (int i = 0; i < 2; i++)
#pragma unroll
        for (int j = 0; j < 8; j++)
#pragma unroll
            for (int r = 0; r < 4; r++) c[i][j][r] = 0.0f;

    const int nchunks = K / BK;
    load_chunk(sb, Ah, Al, Bh, brow, bcol, K, 0, 0, tid);
    CP_COMMIT();
    load_chunk(sb, Ah, Al, Bh, brow, bcol, K, BK, 1, tid);
    CP_COMMIT();

    const int a_r = lane & 15;
    const int a_c = (lane >> 4) << 3;
    const int b_r = ((lane < 16) ? (lane & 7) : (8 + (lane & 7)));
    const int b_c = ((lane >> 3) & 1) << 3;

    for (int ch = 0; ch < nchunks; ch++) {
        if (ch + 1 < nchunks) { CP_WAIT(1); } else { CP_WAIT(0); }
        __syncthreads();
        if (ch + 2 < nchunks) {
            load_chunk(sb, Ah, Al, Bh, brow, bcol, K, (ch + 2) * BK, (ch + 2) % 3, tid);
            CP_COMMIT();
        }
        uint32_t stb = sb + (ch % 3) * STAGE_BYTES;
#pragma unroll
        for (int ks = 0; ks < 2; ks++) {
            const int kb = ks * 16;
            uint32_t ah[2][4], al[2][4], bh[4][4];
#pragma unroll
            for (int mt = 0; mt < 2; mt++) {
                uint32_t ad = stb + SM_AH +
                    (uint32_t)((wm + mt * 16 + a_r) * (PADK * 2) + (kb + a_c) * 2);
                LDSM_X4(ah[mt], ad);
                LDSM_X4(al[mt], ad + (SM_AL - SM_AH));
            }
#pragma unroll
            for (int nt = 0; nt < 4; nt++) {
                uint32_t bd = stb + SM_BH +
                    (uint32_t)((wn + nt * 16 + b_r) * (PADK * 2) + (kb + b_c) * 2);
                LDSM_X4(bh[nt], bd);
            }
            // all h-term MMAs, then all l-term: no back-to-back same accumulator
#pragma unroll
            for (int mt = 0; mt < 2; mt++)
#pragma unroll
                for (int n8 = 0; n8 < 8; n8++)
                    MMA_F16(c[mt][n8], ah[mt],
                            bh[n8 >> 1][(n8 & 1) * 2], bh[n8 >> 1][(n8 & 1) * 2 + 1]);
#pragma unroll
            for (int mt = 0; mt < 2; mt++)
#pragma unroll
                for (int n8 = 0; n8 < 8; n8++)
                    MMA_F16(c[mt][n8], al[mt],
                            bh[n8 >> 1][(n8 & 1) * 2], bh[n8 >> 1][(n8 & 1) * 2 + 1]);
        }
    }

#pragma unroll
    for (int mt = 0; mt < 2; mt++) {
        int row0 = brow + wm + mt * 16 + (lane >> 2);
#pragma unroll
        for (int n8 = 0; n8 < 8; n8++) {
            int col = bcol + wn + n8 * 8 + (lane & 3) * 2;
            if (Chalf) {
                *(__half2*)(Chalf + (size_t)row0 * N + col) =
                    __floats2half2_rn(c[mt][n8][0], c[mt][n8][1]);
                *(__half2*)(Chalf + (size_t)(row0 + 8) * N + col) =
                    __floats2half2_rn(c[mt][n8][2], c[mt][n8][3]);
            } else {
                float bx = 0.f, by = 0.f;
                if (bias) { bx = bias[col]; by = bias[col + 1]; }
                *(float2*)(C + (size_t)row0 * N + col) =
                    make_float2(c[mt][n8][0] + bx, c[mt][n8][1] + by);
                *(float2*)(C + (size_t)(row0 + 8) * N + col) =
                    make_float2(c[mt][n8][2] + bx, c[mt][n8][3] + by);
            }
        }
    }
}

// ---------------- fp32 -> fp16 hi/lo split (x input only) -------------------
__global__ void split_a(const float* __restrict__ src,
                        __half* __restrict__ h, __half* __restrict__ l, int n)
{
    int i = blockIdx.x * blockDim.x + threadIdx.x;
    if (i >= n) return;
    float v = src[i];
    __half hb = __float2half(v);
    h[i] = hb;
    l[i] = __float2half(v - __half2float(hb));
}

// W[K][N] -> Bt[N][K] fp16, smem-tiled transpose
__global__ void wconv(const float* __restrict__ W, __half* __restrict__ Bt, int K, int N)
{
    __shared__ float tile[32][33];
    int n0 = blockIdx.x * 32, k0 = blockIdx.y * 32;
    int tx = threadIdx.x & 31, ty = threadIdx.x >> 5;
#pragma unroll
    for (int r = 0; r < 4; r++)
        tile[ty + 8 * r][tx] = W[(size_t)(k0 + ty + 8 * r) * N + n0 + tx];
    __syncthreads();
#pragma unroll
    for (int r = 0; r < 4; r++)
        Bt[(size_t)(n0 + ty + 8 * r) * K + k0 + tx] = __float2half(tile[tx][ty + 8 * r]);
}

// ---------------- RoPE cos/sin table ----------------------------------------
__global__ void rope_table()
{
    int idx = blockIdx.x * blockDim.x + threadIdx.x;
    if (idx >= TSEQ * 16) return;
    int t = idx >> 4, pg = idx & 15;
    float c0, s0, c1, s1;
    {
        float e = (float)(2 * (2 * pg)) * (1.0f / 64.0f);
        float ang = (float)t * exp2f(-e * 13.2877123795494493f);
        sincosf(ang, &s0, &c0);
    }
    {
        float e = (float)(2 * (2 * pg + 1)) * (1.0f / 64.0f);
        float ang = (float)t * exp2f(-e * 13.2877123795494493f);
        sincosf(ang, &s1, &c1);
    }
    g_rope[idx] = make_float4(c0, s0, c1, s1);
}

// ---------------- QKV pack: rope Q (scaled), rope K, pack V per (b,h) -------
__global__ void qkv_pack()
{
    int idx = blockIdx.x * blockDim.x + threadIdx.x;
    const int total = ROWS * NHEAD * 16;
    if (idx >= total) return;
    int pg = idx & 15;
    int h = (idx >> 4) & (NHEAD - 1);
    int row = idx >> 8;                 // b*TSEQ + t
    int t = row & (TSEQ - 1);
    int b = row >> 11;

    const __half* src = g_qkvh + (size_t)row * QKVCOLS + h * HD;
    size_t dst = ((size_t)(b * NHEAD + h) * TSEQ + t) * HD;
    float4 cs = g_rope[t * 16 + pg];

    // Q: rope + 0.125 scale
    {
        float2 u = __half22float2(*(const __half2*)(src + 2 * pg));
        float2 w = __half22float2(*(const __half2*)(src + 2 * pg + 32));
        *(__half2*)(g_qr + dst + 2 * pg) = __floats2half2_rn(
            0.125f * (u.x * cs.x - w.x * cs.y), 0.125f * (u.y * cs.z - w.y * cs.w));
        *(__half2*)(g_qr + dst + 2 * pg + 32) = __floats2half2_rn(
            0.125f * (u.x * cs.y + w.x * cs.x), 0.125f * (u.y * cs.w + w.y * cs.z));
    }
    // K: rope
    {
        const __half* ks = src + DMODEL;
        float2 u = __half22float2(*(const __half2*)(ks + 2 * pg));
        float2 w = __half22float2(*(const __half2*)(ks + 2 * pg + 32));
        *(__half2*)(g_kr + dst + 2 * pg) = __floats2half2_rn(
            u.x * cs.x - w.x * cs.y, u.y * cs.z - w.y * cs.w);
        *(__half2*)(g_kr + dst + 2 * pg + 32) = __floats2half2_rn(
            u.x * cs.y + w.x * cs.x, u.y * cs.w + w.y * cs.z);
    }
    // V: pack (elements 4*pg .. 4*pg+3)
    *(int2*)(g_vp + dst + 4 * pg) = *(const int2*)(src + 2 * DMODEL + 4 * pg);
}

// ---------------- flash attention via mma.sync -------------------------------
#define PADH 72
#define QS_BYTES (64 * PADH * 2)        // 9216
#define KS_OFF   QS_BYTES
#define KS_BYTES (320 * PADH * 2)       // 46080
#define VS_OFF   (KS_OFF + KS_BYTES)
#define ATTN_SMEM (VS_OFF + KS_BYTES)   // 101376

__global__ __launch_bounds__(256, 2)
void attn_kernel()
{
    extern __shared__ __align__(128) char asmem[];
    uint32_t sb = smem_u32(asmem);
    float* mgb = (float*)(asmem + KS_OFF);   // merge buffer aliases Ks

    const int tid = threadIdx.x, wid = tid >> 5, lane = tid & 31;
    const int b = blockIdx.z, h = blockIdx.y;
    const int t0 = blockIdx.x * 64;
    const int warp_m = wid & 3, warp_n = wid >> 2;

    const size_t bh = (size_t)(b * NHEAD + h) * TSEQ;

    // ---- Q fill: contiguous rows, cp.async
    {
        const __half* qsrc = g_qr + (bh + t0) * HD;
        for (int idx = tid; idx < 64 * 8; idx += 256) {
            int row = idx >> 3, cc = idx & 7;
            cp16(sb + (uint32_t)(row * PADH + cc * 8) * 2, qsrc + row * HD + cc * 8);
        }
    }
    // ---- K/V fill: 320 rows starting t0-128, row-clamped
    {
        const __half* ksrc = g_kr + bh * HD;
        const __half* vsrc = g_vp + bh * HD;
        for (int idx = tid; idx < 320 * 8; idx += 256) {
            int kk = idx >> 3, cc = idx & 7;
            int kg = t0 - 128 + kk;
            kg = kg < 0 ? 0 : (kg > TSEQ - 1 ? TSEQ - 1 : kg);
            cp16(sb + KS_OFF + (uint32_t)(kk * PADH + cc * 8) * 2, ksrc + (size_t)kg * HD + cc * 8);
            cp16(sb + VS_OFF + (uint32_t)(kk * PADH + cc * 8) * 2, vsrc + (size_t)kg * HD + cc * 8);
        }
    }
    CP_COMMIT();
    CP_WAIT(0);
    __syncthreads();

    const int a_r = lane & 15;
    const int a_c = (lane >> 4) << 3;
    const int b_r = ((lane < 16) ? (lane & 7) : (8 + (lane & 7)));
    const int b_c = ((lane >> 3) & 1) << 3;
    const int qlo = t0 + warp_m * 16;
    const int qi0 = qlo + (lane >> 2);

    float m0 = -1e30f, m1 = -1e30f, l0 = 0.f, l1 = 0.f;
    float o[8][4];
#pragma unroll
    for (int t = 0; t < 8; t++)
#pragma unroll
        for (int j = 0; j < 4; j++) o[t][j] = 0.f;

    for (int c = 0; c < 5; c++) {
        int kk0 = 64 * c + 32 * warp_n;
        int kgb = t0 - 128 + kk0;
        if (kgb + 31 < qlo - WIN || kgb > qlo + 15 + WIN) continue;

        float cS[4][4];
#pragma unroll
        for (int i = 0; i < 4; i++)
#pragma unroll
            for (int j = 0; j < 4; j++) cS[i][j] = 0.f;
#pragma unroll
        for (int ks = 0; ks < 4; ks++) {
            uint32_t aq[4], bk0[4], bk1[4];
            LDSM_X4(aq, sb + (uint32_t)((warp_m * 16 + a_r) * PADH + ks * 16 + a_c) * 2);
            LDSM_X4(bk0, sb + KS_OFF + (uint32_t)((kk0 + b_r) * PADH + ks * 16 + b_c) * 2);
            LDSM_X4(bk1, sb + KS_OFF + (uint32_t)((kk0 + 16 + b_r) * PADH + ks * 16 + b_c) * 2);
            MMA_F16(cS[0], aq, bk0[0], bk0[1]);
            MMA_F16(cS[1], aq, bk0[2], bk0[3]);
            MMA_F16(cS[2], aq, bk1[0], bk1[1]);
            MMA_F16(cS[3], aq, bk1[2], bk1[3]);
        }

        float rmax0 = -1e30f, rmax1 = -1e30f;
#pragma unroll
        for (int n8 = 0; n8 < 4; n8++) {
            int jb = kgb + 8 * n8 + 2 * (lane & 3);
#pragma unroll
            for (int e = 0; e < 2; e++) {
                int j = jb + e;
                bool okj = (j >= 0) && (j < TSEQ);
                if (!(okj && j >= qi0 - WIN && j <= qi0 + WIN))         cS[n8][e]     = -1e30f;
                if (!(okj && j >= qi0 + 8 - WIN && j <= qi0 + 8 + WIN)) cS[n8][e + 2] = -1e30f;
            }
            rmax0 = fmaxf(rmax0, fmaxf(cS[n8][0], cS[n8][1]));
            rmax1 = fmaxf(rmax1, fmaxf(cS[n8][2], cS[n8][3]));
        }
        rmax0 = fmaxf(rmax0, __shfl_xor_sync(0xffffffffu, rmax0, 1));
        rmax0 = fmaxf(rmax0, __shfl_xor_sync(0xffffffffu, rmax0, 2));
        rmax1 = fmaxf(rmax1, __shfl_xor_sync(0xffffffffu, rmax1, 1));
        rmax1 = fmaxf(rmax1, __shfl_xor_sync(0xffffffffu, rmax1, 2));

        float mn0 = fmaxf(m0, rmax0), mn1 = fmaxf(m1, rmax1);
        float sc0 = __expf(m0 - mn0), sc1 = __expf(m1 - mn1);
        m0 = mn0; m1 = mn1;

        float ps0 = 0.f, ps1 = 0.f;
        uint32_t pa[4][2];
#pragma unroll
        for (int n8 = 0; n8 < 4; n8++) {
            float p0 = (cS[n8][0] < -1e29f) ? 0.f : __expf(cS[n8][0] - mn0);
            float p1 = (cS[n8][1] < -1e29f) ? 0.f : __expf(cS[n8][1] - mn0);
            float p2 = (cS[n8][2] < -1e29f) ? 0.f : __expf(cS[n8][2] - mn1);
            float p3 = (cS[n8][3] < -1e29f) ? 0.f : __expf(cS[n8][3] - mn1);
            ps0 += p0 + p1; ps1 += p2 + p3;
            pa[n8][0] = packh2(p0, p1);
            pa[n8][1] = packh2(p2, p3);
        }
        ps0 += __shfl_xor_sync(0xffffffffu, ps0, 1);
        ps0 += __shfl_xor_sync(0xffffffffu, ps0, 2);
        ps1 += __shfl_xor_sync(0xffffffffu, ps1, 1);
        ps1 += __shfl_xor_sync(0xffffffffu, ps1, 2);
        l0 = l0 * sc0 + ps0;
        l1 = l1 * sc1 + ps1;
#pragma unroll
        for (int t = 0; t < 8; t++) {
            o[t][0] *= sc0; o[t][1] *= sc0; o[t][2] *= sc1; o[t][3] *= sc1;
        }

#pragma unroll
        for (int kp = 0; kp < 2; kp++) {
            uint32_t a[4] = { pa[2 * kp][0], pa[2 * kp][1], pa[2 * kp + 1][0], pa[2 * kp + 1][1] };
#pragma unroll
            for (int np = 0; np < 4; np++) {
                uint32_t bv[4];
                LDSM_X4_T(bv, sb + VS_OFF +
                    (uint32_t)((kk0 + kp * 16 + a_r) * PADH + np * 16 + a_c) * 2);
                MMA_F16(o[2 * np],     a, bv[0], bv[1]);
                MMA_F16(o[2 * np + 1], a, bv[2], bv[3]);
            }
        }
    }

    __syncthreads();
    float* ob = mgb + (warp_m * 32 + lane) * 33;
    float2* mlb = (float2*)(mgb + 4 * 32 * 33);
    if (warp_n == 1) {
#pragma unroll
        for (int t = 0; t < 8; t++)
#pragma unroll
            for (int j = 0; j < 4; j++) ob[4 * t + j] = o[t][j];
        if ((lane & 3) == 0) {
            mlb[warp_m * 16 + (lane >> 2)]     = make_float2(m0, l0);
            mlb[warp_m * 16 + 8 + (lane >> 2)] = make_float2(m1, l1);
        }
    }
    __syncthreads();
    if (warp_n == 0) {
        float2 M0 = mlb[warp_m * 16 + (lane >> 2)];
        float2 M1 = mlb[warp_m * 16 + 8 + (lane >> 2)];
        float mm0 = fmaxf(m0, M0.x), mm1 = fmaxf(m1, M1.x);
        float w00 = __expf(m0 - mm0), w01 = __expf(M0.x - mm0);
        float w10 = __expf(m1 - mm1), w11 = __expf(M1.x - mm1);
        float inv0 = 1.0f / (l0 * w00 + M0.y * w01);
        float inv1 = 1.0f / (l1 * w10 + M1.y * w11);
        size_t r0 = (size_t)(b * TSEQ + qlo + (lane >> 2)) * DMODEL;
        size_t r1 = r0 + 8 * DMODEL;
#pragma unroll
        for (int t = 0; t < 8; t++) {
            int col = h * HD + t * 8 + 2 * (lane & 3);
            float v0 = (o[t][0] * w00 + ob[4 * t + 0] * w01) * inv0;
            float v1 = (o[t][1] * w00 + ob[4 * t + 1] * w01) * inv0;
            float v2 = (o[t][2] * w10 + ob[4 * t + 2] * w11) * inv1;
            float v3 = (o[t][3] * w10 + ob[4 * t + 3] * w11) * inv1;
            __half h0 = __float2half(v0), h1 = __float2half(v1);
            __half h2 = __float2half(v2), h3 = __float2half(v3);
            *(__half2*)(g_Ah + r0 + col) = __halves2half2(h0, h1);
            *(__half2*)(g_Ah + r1 + col) = __halves2half2(h2, h3);
            *(__half2*)(g_Al + r0 + col) = __halves2half2(
                __float2half(v0 - __half2float(h0)), __float2half(v1 - __half2float(h1)));
            *(__half2*)(g_Al + r1 + col) = __halves2half2(
                __float2half(v2 - __half2float(h2)), __float2half(v3 - __half2float(h3)));
        }
    }
}

// ---------------------------------------------------------------------------
extern "C" void kernel_launch(void* const* d_in, const int* in_sizes, int n_in,
                              void* d_out, int out_size)
{
    const float* x    = (const float*)d_in[0];
    const float* Wqkv = (const float*)d_in[1];
    const float* Wout = (const float*)d_in[2];
    const float* bout = (const float*)d_in[3];
    float* out = (float*)d_out;

    __half *qkvh, *Ah, *Al, *Bh;
    cudaGetSymbolAddress((void**)&qkvh, g_qkvh);
    cudaGetSymbolAddress((void**)&Ah, g_Ah);
    cudaGetSymbolAddress((void**)&Al, g_Al);
    cudaGetSymbolAddress((void**)&Bh, g_Bh);

    cudaFuncSetAttribute(gemm_mma, cudaFuncAttributeMaxDynamicSharedMemorySize, GEMM_SMEM);
    cudaFuncSetAttribute(attn_kernel, cudaFuncAttributeMaxDynamicSharedMemorySize, ATTN_SMEM);

    rope_table<<<(TSEQ * 16 + 255) / 256, 256>>>();

    split_a<<<(ROWS * DMODEL + 511) / 512, 512>>>(x, Ah, Al, ROWS * DMODEL);
    wconv<<<dim3(QKVCOLS / 32, DMODEL / 32), 256>>>(Wqkv, Bh, DMODEL, QKVCOLS);
    gemm_mma<<<dim3(QKVCOLS / BN, ROWS / BM), 256, GEMM_SMEM>>>(
        Ah, Al, Bh, nullptr, qkvh, ROWS, QKVCOLS, DMODEL, nullptr);

    qkv_pack<<<(ROWS * NHEAD * 16 + 255) / 256, 256>>>();
    attn_kernel<<<dim3(TSEQ / 64, NHEAD, NB), 256, ATTN_SMEM>>>();

    wconv<<<dim3(DMODEL / 32, DMODEL / 32), 256>>>(Wout, Bh, DMODEL, DMODEL);
    gemm_mma<<<dim3(DMODEL / BN, ROWS / BM), 256, GEMM_SMEM>>>(
        Ah, Al, Bh, out, nullptr, ROWS, DMODEL, DMODEL, bout);
}